// round 16
// baseline (speedup 1.0000x reference)
#include <cuda_runtime.h>
#include <cuda_fp16.h>
#include <math.h>
#include <stdint.h>

// ---------------------------------------------------------------------------
// Fused NeRF MLP: direct mma.sync.m16n8k16, 3xMMA hi/lo fp16 split.
// 128 samples/CTA, 512 threads, warp grid 4m x 4n (warp tile 32x64).
// A fragments via ldmatrix.x4 from row-major hi/lo planes; B fragments via
// __ldg from pre-split flat fp16 g_whi/g_wlo. No SMEM weight staging.
// ---------------------------------------------------------------------------

#define ROWS     128
#define NTHREADS 512
#define ASTR     328           // activation plane row stride (halves)

#define ABH_O  0               // [128][328] half
#define ABL_O  83968
#define SMEM_TOTAL 167936

#define WTOT 593920
__device__ __align__(16) __half g_whi[WTOT + 256];
__device__ __align__(16) __half g_wlo[WTOT + 256];

#define MMA16816(d, a, b) \
    asm volatile("mma.sync.aligned.m16n8k16.row.col.f32.f16.f16.f32 " \
        "{%0,%1,%2,%3}, {%4,%5,%6,%7}, {%8,%9}, {%0,%1,%2,%3};" \
        : "+f"((d)[0]), "+f"((d)[1]), "+f"((d)[2]), "+f"((d)[3]) \
        : "r"((a)[0]), "r"((a)[1]), "r"((a)[2]), "r"((a)[3]), "r"((b)[0]), "r"((b)[1]))

#define LDM4(r, addr) \
    asm volatile("ldmatrix.sync.aligned.m8n8.x4.shared.b16 {%0,%1,%2,%3}, [%4];" \
        : "=r"((r)[0]), "=r"((r)[1]), "=r"((r)[2]), "=r"((r)[3]) : "r"(addr))

__device__ __forceinline__ uint32_t pack2(float a, float b) {
    __half2 h = __halves2half2(__float2half_rn(a), __float2half_rn(b));
    return *(uint32_t*)&h;
}

// ============================================================================
// Converter: fp32 W[N][Kreal] -> flat fp16 hi/lo, layout cum[L] + n*Kpad + k.
// ============================================================================
__global__ void conv_weights(
    const float* __restrict__ W1, const float* __restrict__ W2,
    const float* __restrict__ W3, const float* __restrict__ W4,
    const float* __restrict__ W5, const float* __restrict__ W6,
    const float* __restrict__ W7, const float* __restrict__ W8,
    const float* __restrict__ Wc, const float* __restrict__ Wd)
{
    const int idx = blockIdx.x * blockDim.x + threadIdx.x;
    if (idx >= WTOT) return;
    const int cum[11] = {0, 16384, 81920, 147456, 212992, 294912,
                         360448, 425984, 491520, 557056, 593920};
    const int kreal[10] = {63, 256, 256, 256, 319, 256, 256, 256, 256, 283};
    const int kpadl[10] = {64, 256, 256, 256, 320, 256, 256, 256, 256, 288};
    const float* Wp[10] = {W1, W2, W3, W4, W5, W6, W7, W8, Wc, Wd};

    int L = 0;
    while (idx >= cum[L + 1]) L++;
    const int e = idx - cum[L];
    const int Kpad = kpadl[L], Kreal = kreal[L];
    const int n = e / Kpad, k = e - n * Kpad;

    const float v = (k < Kreal) ? Wp[L][n * Kreal + k] : 0.0f;
    const __half h = __float2half_rn(v);
    g_whi[idx] = h;
    g_wlo[idx] = __float2half_rn(v - __half2float(h));
}

// ============================================================================
// One layer: out = relu(in @ W^T + b), in place on planes.
// Warp tile 32x64 (2 m-tiles x 8 n-tiles), nt processed in 2 groups of 4.
// ============================================================================
__device__ __forceinline__ void gemm_layer(
    int off, int Kpad, const float* __restrict__ bias,
    __half* __restrict__ aH, __half* __restrict__ aL,
    uint32_t aHs, uint32_t aLs, int N, int tid)
{
    const int wid = tid >> 5, lane = tid & 31;
    const int g = lane >> 2, tig = lane & 3;
    const int wm = wid & 3, wn = wid >> 2;
    const bool act = (wn * 64) < N;
    const int nc = Kpad / 16;
    const int r0 = wm * 32;

    float acc[2][8][4];
#pragma unroll
    for (int mt = 0; mt < 2; mt++)
#pragma unroll
        for (int nt = 0; nt < 8; nt++)
#pragma unroll
            for (int e = 0; e < 4; e++) acc[mt][nt][e] = 0.f;

    if (act) {
        // ldmatrix lane address components (per-thread constant part)
        const uint32_t lrow = (uint32_t)(lane & 15);
        const uint32_t lseg = (uint32_t)(lane >> 4) * 16;   // bytes
        const ptrdiff_t lo = g_wlo - g_whi;
        const __half* wbase = g_whi + off + (wn * 64 + g) * Kpad + 2 * tig;

#pragma unroll 1
        for (int c = 0; c < nc; c++) {
            const int kb = c * 16;
            // A fragments via ldmatrix.x4 (2 m-tiles x hi/lo)
            uint32_t ah[2][4], al[2][4];
#pragma unroll
            for (int mt = 0; mt < 2; mt++) {
                const uint32_t ro = (uint32_t)((r0 + mt * 16) + lrow) * (ASTR * 2)
                                  + (uint32_t)kb * 2 + lseg;
                LDM4(ah[mt], aHs + ro);
                LDM4(al[mt], aLs + ro);
            }
#pragma unroll
            for (int ntg = 0; ntg < 2; ntg++) {
                uint32_t bh[4][2], bl[4][2];
#pragma unroll
                for (int q = 0; q < 4; q++) {
                    const __half* w = wbase + (ntg * 32 + q * 8) * Kpad + kb;
                    bh[q][0] = __ldg((const uint32_t*)(w));
                    bh[q][1] = __ldg((const uint32_t*)(w + 8));
                    bl[q][0] = __ldg((const uint32_t*)(w + lo));
                    bl[q][1] = __ldg((const uint32_t*)(w + lo + 8));
                }
#pragma unroll
                for (int mt = 0; mt < 2; mt++)
#pragma unroll
                    for (int q = 0; q < 4; q++)
                        MMA16816(acc[mt][ntg * 4 + q], ah[mt], bh[q]);
#pragma unroll
                for (int mt = 0; mt < 2; mt++)
#pragma unroll
                    for (int q = 0; q < 4; q++)
                        MMA16816(acc[mt][ntg * 4 + q], al[mt], bh[q]);
#pragma unroll
                for (int mt = 0; mt < 2; mt++)
#pragma unroll
                    for (int q = 0; q < 4; q++)
                        MMA16816(acc[mt][ntg * 4 + q], ah[mt], bl[q]);
            }
        }
    }
    __syncthreads();   // all plane reads done before in-place overwrite

    // epilogue: bias + relu + split -> planes
    if (act) {
#pragma unroll
        for (int mt = 0; mt < 2; mt++) {
            const int r1 = r0 + mt * 16 + g, r2 = r1 + 8;
#pragma unroll
            for (int nt = 0; nt < 8; nt++) {
                const int cc = wn * 64 + nt * 8 + 2 * tig;
                const float b0 = __ldg(&bias[cc]), b1 = __ldg(&bias[cc + 1]);
                const float v0 = fmaxf(acc[mt][nt][0] + b0, 0.f);
                const float v1 = fmaxf(acc[mt][nt][1] + b1, 0.f);
                const float v2 = fmaxf(acc[mt][nt][2] + b0, 0.f);
                const float v3 = fmaxf(acc[mt][nt][3] + b1, 0.f);
                *(uint32_t*)&aH[r1 * ASTR + cc] = pack2(v0, v1);
                *(uint32_t*)&aH[r2 * ASTR + cc] = pack2(v2, v3);
                const float h0 = __half2float(__float2half_rn(v0));
                const float h1 = __half2float(__float2half_rn(v1));
                const float h2 = __half2float(__float2half_rn(v2));
                const float h3 = __half2float(__float2half_rn(v3));
                *(uint32_t*)&aL[r1 * ASTR + cc] = pack2(v0 - h0, v1 - h1);
                *(uint32_t*)&aL[r2 * ASTR + cc] = pack2(v2 - h2, v3 - h3);
            }
        }
    }
    __syncthreads();
}

__global__ void __launch_bounds__(NTHREADS, 1)
nerf_mlp_kernel(
    const float* __restrict__ xw, const float* __restrict__ dd,
    const float* __restrict__ b1, const float* __restrict__ b2,
    const float* __restrict__ b3, const float* __restrict__ b4,
    const float* __restrict__ b5, const float* __restrict__ b6,
    const float* __restrict__ b7, const float* __restrict__ b8,
    const float* __restrict__ Ws, const float* __restrict__ bs,
    const float* __restrict__ bc, const float* __restrict__ bd,
    const float* __restrict__ Wo, const float* __restrict__ bo,
    float* __restrict__ out, int Btot)
{
    extern __shared__ uint8_t sm[];
    __half* aH = (__half*)(sm + ABH_O);
    __half* aL = (__half*)(sm + ABL_O);
    const uint32_t aHs = (uint32_t)__cvta_generic_to_shared(aH);
    const uint32_t aLs = (uint32_t)__cvta_generic_to_shared(aL);

    const int tid  = threadIdx.x;
    const int base = blockIdx.x * ROWS;

    // ---- pe_x -> cols 0..63 and 256..319 ----
    if (tid < ROWS) {
        const int r = tid, g = base + r;
        float f[64];
        f[63] = 0.f;
        const float x = xw[3 * g], y = xw[3 * g + 1], z = xw[3 * g + 2];
        f[0] = x; f[1] = y; f[2] = z;
        float fr = 1.f;
#pragma unroll
        for (int i = 0; i < 10; i++) {
            float sx, cx, sy, cy, sz, cz;
            sincosf(x * fr, &sx, &cx); sincosf(y * fr, &sy, &cy); sincosf(z * fr, &sz, &cz);
            const int o = 3 + 6 * i;
            f[o] = sx; f[o+1] = sy; f[o+2] = sz; f[o+3] = cx; f[o+4] = cy; f[o+5] = cz;
            fr *= 2.f;
        }
#pragma unroll
        for (int j = 0; j < 64; j++) {
            const __half h = __float2half_rn(f[j]);
            const __half l = __float2half_rn(f[j] - __half2float(h));
            aH[r * ASTR + j] = h;        aL[r * ASTR + j] = l;
            aH[r * ASTR + 256 + j] = h;  aL[r * ASTR + 256 + j] = l;
        }
    }
    __syncthreads();

    const int off[10]  = {0, 16384, 81920, 147456, 212992,
                          294912, 360448, 425984, 491520, 557056};
    const int kpad[10] = {64, 256, 256, 256, 320, 256, 256, 256, 256, 288};

    // ---- trunk ----
    gemm_layer(off[0], kpad[0], b1, aH, aL, aHs, aLs, 256, tid);
    gemm_layer(off[1], kpad[1], b2, aH, aL, aHs, aLs, 256, tid);
    gemm_layer(off[2], kpad[2], b3, aH, aL, aHs, aLs, 256, tid);
    gemm_layer(off[3], kpad[3], b4, aH, aL, aHs, aLs, 256, tid);
    gemm_layer(off[4], kpad[4], b5, aH, aL, aHs, aLs, 256, tid);   // skip-concat
    gemm_layer(off[5], kpad[5], b6, aH, aL, aHs, aLs, 256, tid);
    gemm_layer(off[6], kpad[6], b7, aH, aL, aHs, aLs, 256, tid);
    gemm_layer(off[7], kpad[7], b8, aH, aL, aHs, aLs, 256, tid);

    // ---- sigma head (h8 in cols 0..255) ----
    if (tid < ROWS) {
        const int r = tid;
        float acc = __ldg(&bs[0]);
#pragma unroll 8
        for (int k = 0; k < 256; k++) {
            const float v = __half2float(aH[r * ASTR + k]) + __half2float(aL[r * ASTR + k]);
            acc = fmaf(__ldg(&Ws[k]), v, acc);
        }
        out[(size_t)3 * Btot + base + r] = fmaxf(acc, 0.f);
    }
    __syncthreads();

    // ---- color branch ----
    gemm_layer(off[8], kpad[8], bc, aH, aL, aHs, aLs, 256, tid);
    // recompute pe_d -> cols 256..282, zeros 283..287
    if (tid < ROWS) {
        const int r = tid, g = base + r;
        float q[27];
        float dx = dd[3 * g], dy = dd[3 * g + 1], dz = dd[3 * g + 2];
        const float inv = 1.f / (sqrtf(dx * dx + dy * dy + dz * dz) + 1e-8f);
        dx *= inv; dy *= inv; dz *= inv;
        q[0] = dx; q[1] = dy; q[2] = dz;
        float fr = 1.f;
#pragma unroll
        for (int i = 0; i < 4; i++) {
            float sx, cx, sy, cy, sz, cz;
            sincosf(dx * fr, &sx, &cx); sincosf(dy * fr, &sy, &cy); sincosf(dz * fr, &sz, &cz);
            const int o = 3 + 6 * i;
            q[o] = sx; q[o+1] = sy; q[o+2] = sz; q[o+3] = cx; q[o+4] = cy; q[o+5] = cz;
            fr *= 2.f;
        }
#pragma unroll
        for (int j = 0; j < 27; j++) {
            const __half h = __float2half_rn(q[j]);
            aH[r * ASTR + 256 + j] = h;
            aL[r * ASTR + 256 + j] = __float2half_rn(q[j] - __half2float(h));
        }
#pragma unroll
        for (int j = 27; j < 32; j++) {
            aH[r * ASTR + 256 + j] = __float2half_rn(0.f);
            aL[r * ASTR + 256 + j] = __float2half_rn(0.f);
        }
    }
    __syncthreads();
    gemm_layer(off[9], kpad[9], bd, aH, aL, aHs, aLs, 128, tid);

    // ---- rgb head (hcd in cols 0..127) ----
    if (tid < ROWS) {
        const int r = tid, g = base + r;
#pragma unroll
        for (int c = 0; c < 3; c++) {
            float acc = __ldg(&bo[c]);
#pragma unroll 8
            for (int k = 0; k < 128; k++) {
                const float v = __half2float(aH[r * ASTR + k]) + __half2float(aL[r * ASTR + k]);
                acc = fmaf(__ldg(&Wo[c * 128 + k]), v, acc);
            }
            out[(size_t)3 * g + c] = 1.f / (1.f + expf(-acc));
        }
    }
}

extern "C" void kernel_launch(void* const* d_in, const int* in_sizes, int n_in,
                              void* d_out, int out_size)
{
    const int Btot = in_sizes[0] / 3;

    conv_weights<<<(WTOT + 255) / 256, 256>>>(
        (const float*)d_in[2],  (const float*)d_in[4],
        (const float*)d_in[6],  (const float*)d_in[8],
        (const float*)d_in[10], (const float*)d_in[12],
        (const float*)d_in[14], (const float*)d_in[16],
        (const float*)d_in[20], (const float*)d_in[22]);

    cudaFuncSetAttribute(nerf_mlp_kernel,
                         cudaFuncAttributeMaxDynamicSharedMemorySize, SMEM_TOTAL);

    nerf_mlp_kernel<<<Btot / ROWS, NTHREADS, SMEM_TOTAL>>>(
        (const float*)d_in[0],  (const float*)d_in[1],
        (const float*)d_in[3],  (const float*)d_in[5],
        (const float*)d_in[7],  (const float*)d_in[9],
        (const float*)d_in[11], (const float*)d_in[13],
        (const float*)d_in[15], (const float*)d_in[17],
        (const float*)d_in[18], (const float*)d_in[19],
        (const float*)d_in[21], (const float*)d_in[23],
        (const float*)d_in[24], (const float*)d_in[25],
        (float*)d_out, Btot);
}

// round 17
// speedup vs baseline: 1.7045x; 1.7045x over previous
#include <cuda_runtime.h>
#include <cuda_fp16.h>
#include <math.h>
#include <stdint.h>

// ---------------------------------------------------------------------------
// Fused NeRF MLP: direct mma.sync.m16n8k16, 3xMMA hi/lo fp16 split.
// 128 samples/CTA, 512 threads, warp grid 2m x 8n (warp tile 64x32).
// A: interleaved hi/lo planes, 8B units {hi2,lo2}, LDS.64 fragment loads.
// B: pre-packed fragment-order blob, one LDG.128 per n-tile per chunk.
// ---------------------------------------------------------------------------

#define ROWS     128
#define NTHREADS 512
#define ASU      164           // A row stride in 8B units (164*8=1312B; ≡32 mod 128)

#define SMEM_TOTAL (128 * ASU * 8)   // 167936

#define TOT_U 148480           // blob total 16B units
__device__ __align__(16) uint4 g_wblob[TOT_U + 32];

#define MMA16816(d, a, b) \
    asm volatile("mma.sync.aligned.m16n8k16.row.col.f32.f16.f16.f32 " \
        "{%0,%1,%2,%3}, {%4,%5,%6,%7}, {%8,%9}, {%0,%1,%2,%3};" \
        : "+f"((d)[0]), "+f"((d)[1]), "+f"((d)[2]), "+f"((d)[3]) \
        : "r"((a)[0]), "r"((a)[1]), "r"((a)[2]), "r"((a)[3]), "r"((b)[0]), "r"((b)[1]))

__device__ __forceinline__ uint32_t pack2(float a, float b) {
    __half2 h = __halves2half2(__float2half_rn(a), __float2half_rn(b));
    return *(uint32_t*)&h;
}

// layer tables (shared by converter and main kernel)
__device__ __constant__ int c_offU[10] = {0, 4096, 20480, 36864, 53248,
                                          73728, 90112, 106496, 122880, 139264};
__device__ __constant__ int c_ncL[10]  = {4, 16, 16, 16, 20, 16, 16, 16, 16, 18};
__device__ __constant__ int c_krl[10]  = {63, 256, 256, 256, 319, 256, 256, 256, 256, 283};

// ============================================================================
// Converter: fp32 W[N][Kreal] -> fragment-order blob.
// Unit (L, t, c, lane): g=lane>>2, tig=lane&3, n=t*8+g, k0=c*16+2tig,
// k1=k0+8; content {hi(k0),hi(k0+1)} {hi(k1),hi(k1+1)} {lo...} {lo...}.
// ============================================================================
__global__ void conv_weights(
    const float* __restrict__ W1, const float* __restrict__ W2,
    const float* __restrict__ W3, const float* __restrict__ W4,
    const float* __restrict__ W5, const float* __restrict__ W6,
    const float* __restrict__ W7, const float* __restrict__ W8,
    const float* __restrict__ Wc, const float* __restrict__ Wd)
{
    const int idx = blockIdx.x * blockDim.x + threadIdx.x;
    if (idx >= TOT_U) return;
    const float* Wp[10] = {W1, W2, W3, W4, W5, W6, W7, W8, Wc, Wd};

    int L = 9;
#pragma unroll
    for (int l = 0; l < 9; l++)
        if (idx < c_offU[l + 1]) { L = l; break; }
    const int rem = idx - c_offU[L];
    const int nc = c_ncL[L], Kreal = c_krl[L];
    const int blk = rem >> 5, lane = rem & 31;
    const int t = blk / nc, c = blk - t * nc;
    const int g = lane >> 2, tig = lane & 3;
    const int n = t * 8 + g;
    const int k0 = c * 16 + 2 * tig;
    const int k1 = k0 + 8;
    const float* Wl = Wp[L];

    float v[4];
    v[0] = (k0     < Kreal) ? Wl[n * Kreal + k0]     : 0.f;
    v[1] = (k0 + 1 < Kreal) ? Wl[n * Kreal + k0 + 1] : 0.f;
    v[2] = (k1     < Kreal) ? Wl[n * Kreal + k1]     : 0.f;
    v[3] = (k1 + 1 < Kreal) ? Wl[n * Kreal + k1 + 1] : 0.f;

    float h[4];
#pragma unroll
    for (int i = 0; i < 4; i++) h[i] = __half2float(__float2half_rn(v[i]));

    uint4 u;
    u.x = pack2(v[0], v[1]);
    u.y = pack2(v[2], v[3]);
    u.z = pack2(v[0] - h[0], v[1] - h[1]);
    u.w = pack2(v[2] - h[2], v[3] - h[3]);
    g_wblob[idx] = u;
}

// ============================================================================
// One layer: out = relu(in @ W^T + b), in place on interleaved A units.
// Warp tile 64m x 32n (4 m-tiles, 4 n-tiles). N = 256 or 128.
// ============================================================================
__device__ __forceinline__ void gemm_layer(
    int Lidx, const float* __restrict__ bias,
    uint2* __restrict__ aU, int N, int tid)
{
    const int wid = tid >> 5, lane = tid & 31;
    const int g = lane >> 2, tig = lane & 3;
    const int wm = wid & 1, wn = wid >> 1;
    const bool act = (wn * 32) < N;
    const int nc = c_ncL[Lidx];
    const uint4* __restrict__ bp = g_wblob + c_offU[Lidx];

    float acc[4][4][4];
#pragma unroll
    for (int mt = 0; mt < 4; mt++)
#pragma unroll
        for (int nt = 0; nt < 4; nt++)
#pragma unroll
            for (int e = 0; e < 4; e++) acc[mt][nt][e] = 0.f;

    if (act) {
#pragma unroll 2
        for (int c = 0; c < nc; c++) {
            const int ku = c * 8 + tig;
            // B: one LDG.128 per n-tile
            uint4 bw[4];
#pragma unroll
            for (int q = 0; q < 4; q++)
                bw[q] = __ldg(&bp[((wn * 4 + q) * nc + c) * 32 + lane]);
            // A: LDS.64 units -> (hi, lo) register pairs
            uint32_t ah[4][4], al[4][4];
#pragma unroll
            for (int mt = 0; mt < 4; mt++) {
                const int r1 = wm * 64 + mt * 16 + g, r2 = r1 + 8;
                const uint2 u00 = aU[r1 * ASU + ku];
                const uint2 u10 = aU[r2 * ASU + ku];
                const uint2 u01 = aU[r1 * ASU + ku + 4];
                const uint2 u11 = aU[r2 * ASU + ku + 4];
                ah[mt][0] = u00.x; al[mt][0] = u00.y;
                ah[mt][1] = u10.x; al[mt][1] = u10.y;
                ah[mt][2] = u01.x; al[mt][2] = u01.y;
                ah[mt][3] = u11.x; al[mt][3] = u11.y;
            }
            uint32_t bh[4][2], bl[4][2];
#pragma unroll
            for (int q = 0; q < 4; q++) {
                bh[q][0] = bw[q].x; bh[q][1] = bw[q].y;
                bl[q][0] = bw[q].z; bl[q][1] = bw[q].w;
            }
#pragma unroll
            for (int mt = 0; mt < 4; mt++)
#pragma unroll
                for (int q = 0; q < 4; q++)
                    MMA16816(acc[mt][q], ah[mt], bh[q]);
#pragma unroll
            for (int mt = 0; mt < 4; mt++)
#pragma unroll
                for (int q = 0; q < 4; q++)
                    MMA16816(acc[mt][q], al[mt], bh[q]);
#pragma unroll
            for (int mt = 0; mt < 4; mt++)
#pragma unroll
                for (int q = 0; q < 4; q++)
                    MMA16816(acc[mt][q], ah[mt], bl[q]);
        }
    }
    __syncthreads();   // all A reads done before in-place overwrite

    // epilogue: bias + relu + split -> interleaved units (STS.64)
    if (act) {
#pragma unroll
        for (int mt = 0; mt < 4; mt++) {
            const int r1 = wm * 64 + mt * 16 + g, r2 = r1 + 8;
#pragma unroll
            for (int nt = 0; nt < 4; nt++) {
                const int cc = wn * 32 + nt * 8 + 2 * tig;
                const float b0 = __ldg(&bias[cc]), b1 = __ldg(&bias[cc + 1]);
                const float v0 = fmaxf(acc[mt][nt][0] + b0, 0.f);
                const float v1 = fmaxf(acc[mt][nt][1] + b1, 0.f);
                const float v2 = fmaxf(acc[mt][nt][2] + b0, 0.f);
                const float v3 = fmaxf(acc[mt][nt][3] + b1, 0.f);
                const float h0 = __half2float(__float2half_rn(v0));
                const float h1 = __half2float(__float2half_rn(v1));
                const float h2 = __half2float(__float2half_rn(v2));
                const float h3 = __half2float(__float2half_rn(v3));
                uint2 u1, u2;
                u1.x = pack2(v0, v1); u1.y = pack2(v0 - h0, v1 - h1);
                u2.x = pack2(v2, v3); u2.y = pack2(v2 - h2, v3 - h3);
                aU[r1 * ASU + cc / 2] = u1;
                aU[r2 * ASU + cc / 2] = u2;
            }
        }
    }
    __syncthreads();
}

__global__ void __launch_bounds__(NTHREADS, 1)
nerf_mlp_kernel(
    const float* __restrict__ xw, const float* __restrict__ dd,
    const float* __restrict__ b1, const float* __restrict__ b2,
    const float* __restrict__ b3, const float* __restrict__ b4,
    const float* __restrict__ b5, const float* __restrict__ b6,
    const float* __restrict__ b7, const float* __restrict__ b8,
    const float* __restrict__ Ws, const float* __restrict__ bs,
    const float* __restrict__ bc, const float* __restrict__ bd,
    const float* __restrict__ Wo, const float* __restrict__ bo,
    float* __restrict__ out, int Btot)
{
    extern __shared__ uint8_t sm[];
    uint2* aU = (uint2*)sm;

    const int tid  = threadIdx.x;
    const int base = blockIdx.x * ROWS;

    // ---- pe_x -> units 0..31 (cols 0..63) and 128..159 (cols 256..319) ----
    if (tid < ROWS) {
        const int r = tid, g = base + r;
        float f[64];
        f[63] = 0.f;
        const float x = xw[3 * g], y = xw[3 * g + 1], z = xw[3 * g + 2];
        f[0] = x; f[1] = y; f[2] = z;
        float fr = 1.f;
#pragma unroll
        for (int i = 0; i < 10; i++) {
            float sx, cx, sy, cy, sz, cz;
            sincosf(x * fr, &sx, &cx); sincosf(y * fr, &sy, &cy); sincosf(z * fr, &sz, &cz);
            const int o = 3 + 6 * i;
            f[o] = sx; f[o+1] = sy; f[o+2] = sz; f[o+3] = cx; f[o+4] = cy; f[o+5] = cz;
            fr *= 2.f;
        }
#pragma unroll
        for (int j = 0; j < 64; j += 2) {
            const float h0 = __half2float(__float2half_rn(f[j]));
            const float h1 = __half2float(__float2half_rn(f[j + 1]));
            uint2 u;
            u.x = pack2(f[j], f[j + 1]);
            u.y = pack2(f[j] - h0, f[j + 1] - h1);
            aU[r * ASU + j / 2] = u;
            aU[r * ASU + 128 + j / 2] = u;
        }
    }
    __syncthreads();

    // ---- trunk ----
    gemm_layer(0, b1, aU, 256, tid);
    gemm_layer(1, b2, aU, 256, tid);
    gemm_layer(2, b3, aU, 256, tid);
    gemm_layer(3, b4, aU, 256, tid);
    gemm_layer(4, b5, aU, 256, tid);   // skip-concat (pe_x in units 128..159)
    gemm_layer(5, b6, aU, 256, tid);
    gemm_layer(6, b7, aU, 256, tid);
    gemm_layer(7, b8, aU, 256, tid);

    // ---- sigma head (h8 in cols 0..255) ----
    if (tid < ROWS) {
        const int r = tid;
        float acc = __ldg(&bs[0]);
#pragma unroll 8
        for (int k = 0; k < 256; k += 2) {
            const uint2 u = aU[r * ASU + k / 2];
            const __half2 hp = *(const __half2*)&u.x;
            const __half2 lp = *(const __half2*)&u.y;
            acc = fmaf(__ldg(&Ws[k]),     __half2float(__low2half(hp))  + __half2float(__low2half(lp)),  acc);
            acc = fmaf(__ldg(&Ws[k + 1]), __half2float(__high2half(hp)) + __half2float(__high2half(lp)), acc);
        }
        out[(size_t)3 * Btot + base + r] = fmaxf(acc, 0.f);
    }
    __syncthreads();

    // ---- color branch ----
    gemm_layer(8, bc, aU, 256, tid);
    // recompute pe_d -> cols 256..282 (units 128..143), zeros 283..287
    if (tid < ROWS) {
        const int r = tid, g = base + r;
        float q[32];
#pragma unroll
        for (int j = 27; j < 32; j++) q[j] = 0.f;
        float dx = dd[3 * g], dy = dd[3 * g + 1], dz = dd[3 * g + 2];
        const float inv = 1.f / (sqrtf(dx * dx + dy * dy + dz * dz) + 1e-8f);
        dx *= inv; dy *= inv; dz *= inv;
        q[0] = dx; q[1] = dy; q[2] = dz;
        float fr = 1.f;
#pragma unroll
        for (int i = 0; i < 4; i++) {
            float sx, cx, sy, cy, sz, cz;
            sincosf(dx * fr, &sx, &cx); sincosf(dy * fr, &sy, &cy); sincosf(dz * fr, &sz, &cz);
            const int o = 3 + 6 * i;
            q[o] = sx; q[o+1] = sy; q[o+2] = sz; q[o+3] = cx; q[o+4] = cy; q[o+5] = cz;
            fr *= 2.f;
        }
#pragma unroll
        for (int j = 0; j < 32; j += 2) {
            const float h0 = __half2float(__float2half_rn(q[j]));
            const float h1 = __half2float(__float2half_rn(q[j + 1]));
            uint2 u;
            u.x = pack2(q[j], q[j + 1]);
            u.y = pack2(q[j] - h0, q[j + 1] - h1);
            aU[r * ASU + 128 + j / 2] = u;
        }
    }
    __syncthreads();
    gemm_layer(9, bd, aU, 128, tid);

    // ---- rgb head (hcd in cols 0..127) ----
    if (tid < ROWS) {
        const int r = tid, g = base + r;
#pragma unroll
        for (int c = 0; c < 3; c++) {
            float acc = __ldg(&bo[c]);
#pragma unroll 8
            for (int k = 0; k < 128; k += 2) {
                const uint2 u = aU[r * ASU + k / 2];
                const __half2 hp = *(const __half2*)&u.x;
                const __half2 lp = *(const __half2*)&u.y;
                acc = fmaf(__ldg(&Wo[c * 128 + k]),
                           __half2float(__low2half(hp)) + __half2float(__low2half(lp)), acc);
                acc = fmaf(__ldg(&Wo[c * 128 + k + 1]),
                           __half2float(__high2half(hp)) + __half2float(__high2half(lp)), acc);
            }
            out[(size_t)3 * g + c] = 1.f / (1.f + expf(-acc));
        }
    }
}

extern "C" void kernel_launch(void* const* d_in, const int* in_sizes, int n_in,
                              void* d_out, int out_size)
{
    const int Btot = in_sizes[0] / 3;

    conv_weights<<<(TOT_U + 255) / 256, 256>>>(
        (const float*)d_in[2],  (const float*)d_in[4],
        (const float*)d_in[6],  (const float*)d_in[8],
        (const float*)d_in[10], (const float*)d_in[12],
        (const float*)d_in[14], (const float*)d_in[16],
        (const float*)d_in[20], (const float*)d_in[22]);

    cudaFuncSetAttribute(nerf_mlp_kernel,
                         cudaFuncAttributeMaxDynamicSharedMemorySize, SMEM_TOTAL);

    nerf_mlp_kernel<<<Btot / ROWS, NTHREADS, SMEM_TOTAL>>>(
        (const float*)d_in[0],  (const float*)d_in[1],
        (const float*)d_in[3],  (const float*)d_in[5],
        (const float*)d_in[7],  (const float*)d_in[9],
        (const float*)d_in[11], (const float*)d_in[13],
        (const float*)d_in[15], (const float*)d_in[17],
        (const float*)d_in[18], (const float*)d_in[19],
        (const float*)d_in[21], (const float*)d_in[23],
        (const float*)d_in[24], (const float*)d_in[25],
        (float*)d_out, Btot);
}